// round 2
// baseline (speedup 1.0000x reference)
#include <cuda_runtime.h>
#include <cuda_bf16.h>

// k_i = exp(-c_i^2), c_i = -2 + 0.25*i  (double-evaluated literals)
__constant__ float K_EXP[16] = {
    0.01831563889245985f, 0.04677062238395898f, 0.10539922456186433f, 0.20961138667265397f,
    0.36787944117144233f, 0.56978282473092210f, 0.77880078307140487f, 0.93941306281347579f,
    1.00000000000000000f, 0.93941306281347579f, 0.77880078307140487f, 0.56978282473092210f,
    0.36787944117144233f, 0.20961138667265397f, 0.10539922456186433f, 0.04677062238395898f
};

// exp(-d) rounds to 1.0f for d <= ~2^-25: tied softmax weights -> argmax picks lower index.
#define TIE_EPS 2.9802322387695312e-8f   // 2^-25

__device__ __forceinline__ void quantize_one(float xv, float& qh, float& qs, int& idx)
{
    // --- hard assignment, replicating reference fp32 boundary behavior ---
    float t = fmaf(xv, 4.0f, 8.0f);
    int lo = (int)floorf(t);
    lo = max(0, min(lo, 15));
    int hi = min(lo + 1, 15);

    float clo = fmaf((float)lo, 0.25f, -2.0f);
    float chi = fmaf((float)hi, 0.25f, -2.0f);
    float dlo = __fsub_rn(xv, clo);
    float dhi = __fsub_rn(xv, chi);
    float plo = __fmul_rn(dlo, dlo);     // same ops/rounding as reference phi
    float phi_ = __fmul_rn(dhi, dhi);

    // hi wins only if its exp weight is strictly greater after fp32 exp rounding
    idx = (__fsub_rn(plo, phi_) > TIE_EPS) ? hi : lo;
    qh = fmaf((float)idx, 0.25f, -2.0f);

    // --- soft assignment: w_i ∝ exp(0.5*x)^i * exp(-c_i^2) ---
    float r = __expf(0.5f * xv);
    float p = 1.0f;
    float num = 0.0f, den = 0.0f;
#pragma unroll
    for (int i = 0; i < 16; ++i) {
        float u = K_EXP[i] * p;
        den += u;
        float ci = fmaf((float)i, 0.25f, -2.0f);   // compile-time constant after unroll
        num = fmaf(ci, u, num);
        p *= r;
    }
    qs = __fdividef(num, den);
}

__device__ __forceinline__ void write_onehot(float4* oh, int idx)
{
    float4 a, b, c, d;
    a.x = (idx ==  0) ? 1.0f : 0.0f;  a.y = (idx ==  1) ? 1.0f : 0.0f;
    a.z = (idx ==  2) ? 1.0f : 0.0f;  a.w = (idx ==  3) ? 1.0f : 0.0f;
    b.x = (idx ==  4) ? 1.0f : 0.0f;  b.y = (idx ==  5) ? 1.0f : 0.0f;
    b.z = (idx ==  6) ? 1.0f : 0.0f;  b.w = (idx ==  7) ? 1.0f : 0.0f;
    c.x = (idx ==  8) ? 1.0f : 0.0f;  c.y = (idx ==  9) ? 1.0f : 0.0f;
    c.z = (idx == 10) ? 1.0f : 0.0f;  c.w = (idx == 11) ? 1.0f : 0.0f;
    d.x = (idx == 12) ? 1.0f : 0.0f;  d.y = (idx == 13) ? 1.0f : 0.0f;
    d.z = (idx == 14) ? 1.0f : 0.0f;  d.w = (idx == 15) ? 1.0f : 0.0f;
    oh[0] = a; oh[1] = b; oh[2] = c; oh[3] = d;
}

__global__ void Quantize_29437705847334_kernel(
    const float* __restrict__ x,
    float* __restrict__ qbar,
    float* __restrict__ qhard,
    float* __restrict__ qsoft,
    float* __restrict__ onehot,
    int n)
{
    int t = blockIdx.x * blockDim.x + threadIdx.x;
    int e4 = t * 4;
    if (e4 >= n) return;

    if (e4 + 3 < n) {
        float4 xv = *reinterpret_cast<const float4*>(x + e4);
        float qh0, qh1, qh2, qh3, qs0, qs1, qs2, qs3;
        int i0, i1, i2, i3;
        quantize_one(xv.x, qh0, qs0, i0);
        quantize_one(xv.y, qh1, qs1, i1);
        quantize_one(xv.z, qh2, qs2, i2);
        quantize_one(xv.w, qh3, qs3, i3);

        float4 qh = make_float4(qh0, qh1, qh2, qh3);
        float4 qs = make_float4(qs0, qs1, qs2, qs3);
        *reinterpret_cast<float4*>(qbar  + e4) = qh;
        *reinterpret_cast<float4*>(qhard + e4) = qh;
        *reinterpret_cast<float4*>(qsoft + e4) = qs;

        float4* oh = reinterpret_cast<float4*>(onehot + (size_t)e4 * 16);
        write_onehot(oh +  0, i0);
        write_onehot(oh +  4, i1);
        write_onehot(oh +  8, i2);
        write_onehot(oh + 12, i3);
    } else {
        for (int e = e4; e < n; ++e) {
            float qh, qs; int idx;
            quantize_one(x[e], qh, qs, idx);
            qbar[e]  = qh;
            qhard[e] = qh;
            qsoft[e] = qs;
            float4* oh = reinterpret_cast<float4*>(onehot + (size_t)e * 16);
            write_onehot(oh, idx);
        }
    }
}

extern "C" void kernel_launch(void* const* d_in, const int* in_sizes, int n_in,
                              void* d_out, int out_size)
{
    const float* x = (const float*)d_in[0];
    int n = in_sizes[0];                 // 4,194,304 elements

    float* out    = (float*)d_out;
    float* qbar   = out;
    float* qhard  = out + (size_t)n;
    float* qsoft  = out + (size_t)2 * n;
    float* onehot = out + (size_t)3 * n;

    int threads = 256;
    int elems_per_thread = 4;
    int blocks = (n + threads * elems_per_thread - 1) / (threads * elems_per_thread);
    Quantize_29437705847334_kernel<<<blocks, threads>>>(x, qbar, qhard, qsoft, onehot, n);
}

// round 3
// speedup vs baseline: 2.0480x; 2.0480x over previous
#include <cuda_runtime.h>
#include <cuda_bf16.h>

// k_i = exp(-c_i^2), c_i = -2 + 0.25*i  (double-evaluated literals)
__constant__ float K_EXP[16] = {
    0.01831563889245985f, 0.04677062238395898f, 0.10539922456186433f, 0.20961138667265397f,
    0.36787944117144233f, 0.56978282473092210f, 0.77880078307140487f, 0.93941306281347579f,
    1.00000000000000000f, 0.93941306281347579f, 0.77880078307140487f, 0.56978282473092210f,
    0.36787944117144233f, 0.20961138667265397f, 0.10539922456186433f, 0.04677062238395898f
};

// exp(-d) rounds to 1.0f for d <= ~2^-25: tied softmax weights -> argmax picks lower index.
#define TIE_EPS 2.9802322387695312e-8f   // 2^-25

__device__ __forceinline__ void quantize_one(float xv, float& qh, float& qs, int& idx)
{
    // --- hard assignment, replicating reference fp32 boundary behavior ---
    float t = fmaf(xv, 4.0f, 8.0f);
    int lo = (int)floorf(t);
    lo = max(0, min(lo, 15));
    int hi = min(lo + 1, 15);

    float clo = fmaf((float)lo, 0.25f, -2.0f);
    float chi = fmaf((float)hi, 0.25f, -2.0f);
    float dlo = __fsub_rn(xv, clo);
    float dhi = __fsub_rn(xv, chi);
    float plo  = __fmul_rn(dlo, dlo);    // same ops/rounding as reference phi
    float phi_ = __fmul_rn(dhi, dhi);

    // hi wins only if its exp weight is strictly greater after fp32 exp rounding
    idx = (__fsub_rn(plo, phi_) > TIE_EPS) ? hi : lo;
    qh = fmaf((float)idx, 0.25f, -2.0f);

    // --- soft assignment: w_i ∝ exp(0.5*x)^i * exp(-c_i^2) ---
    float r = __expf(0.5f * xv);
    float p = 1.0f;
    float num = 0.0f, den = 0.0f;
#pragma unroll
    for (int i = 0; i < 16; ++i) {
        float u = K_EXP[i] * p;
        den += u;
        float ci = fmaf((float)i, 0.25f, -2.0f);   // compile-time constant after unroll
        num = fmaf(ci, u, num);
        p *= r;
    }
    qs = __fdividef(num, den);
}

// Each warp handles 128 contiguous elements (4 per lane via float4).
// one_hot (128 rows x 64B = 8KB contiguous) is written with fully coalesced
// STG.128: iteration j, lane l writes float4 #(j*32+l); the element index
// needed is fetched by one shfl from the owning lane's packed 16-bit word.
__global__ void Quantize_29437705847334_kernel(
    const float* __restrict__ x,
    float* __restrict__ qbar,
    float* __restrict__ qhard,
    float* __restrict__ qsoft,
    float* __restrict__ onehot,
    int n)
{
    int lane = threadIdx.x & 31;
    int warp_id = (blockIdx.x * blockDim.x + threadIdx.x) >> 5;
    size_t base = (size_t)warp_id * 128;          // warp's first element
    if (base >= (size_t)n) return;

    if (base + 128 <= (size_t)n) {
        size_t e4 = base + (size_t)lane * 4;
        float4 xv = *reinterpret_cast<const float4*>(x + e4);

        float qh0, qh1, qh2, qh3, qs0, qs1, qs2, qs3;
        int i0, i1, i2, i3;
        quantize_one(xv.x, qh0, qs0, i0);
        quantize_one(xv.y, qh1, qs1, i1);
        quantize_one(xv.z, qh2, qs2, i2);
        quantize_one(xv.w, qh3, qs3, i3);

        float4 qh = make_float4(qh0, qh1, qh2, qh3);
        float4 qs = make_float4(qs0, qs1, qs2, qs3);
        *reinterpret_cast<float4*>(qbar  + e4) = qh;
        *reinterpret_cast<float4*>(qhard + e4) = qh;
        *reinterpret_cast<float4*>(qsoft + e4) = qs;

        unsigned pack = (unsigned)i0 | ((unsigned)i1 << 4) |
                        ((unsigned)i2 << 8) | ((unsigned)i3 << 12);

        float4* oh = reinterpret_cast<float4*>(onehot + base * 16);
#pragma unroll
        for (int j = 0; j < 16; ++j) {
            int g   = j * 32 + lane;          // float4 slot within warp's 8KB run
            int e   = g >> 2;                 // element 0..127 within warp
            int q4  = (g & 3) << 2;           // first center of this quad
            unsigned pk = __shfl_sync(0xffffffffu, pack, e >> 2);
            int idx_e = (int)((pk >> ((e & 3) * 4)) & 15u);
            float4 v;
            v.x = (idx_e == q4 + 0) ? 1.0f : 0.0f;
            v.y = (idx_e == q4 + 1) ? 1.0f : 0.0f;
            v.z = (idx_e == q4 + 2) ? 1.0f : 0.0f;
            v.w = (idx_e == q4 + 3) ? 1.0f : 0.0f;
            oh[g] = v;
        }
    } else {
        // scalar tail (n not a multiple of 128)
        for (size_t e = base + lane; e < (size_t)n; e += 32) {
            float qh, qs; int idx;
            quantize_one(x[e], qh, qs, idx);
            qbar[e]  = qh;
            qhard[e] = qh;
            qsoft[e] = qs;
            float* oh = onehot + e * 16;
#pragma unroll
            for (int i = 0; i < 16; ++i) oh[i] = (i == idx) ? 1.0f : 0.0f;
        }
    }
}

extern "C" void kernel_launch(void* const* d_in, const int* in_sizes, int n_in,
                              void* d_out, int out_size)
{
    const float* x = (const float*)d_in[0];
    int n = in_sizes[0];                 // 4,194,304 elements

    float* out    = (float*)d_out;
    float* qbar   = out;
    float* qhard  = out + (size_t)n;
    float* qsoft  = out + (size_t)2 * n;
    float* onehot = out + (size_t)3 * n;

    int warps = (n + 127) / 128;
    int threads = 256;                   // 8 warps/block
    int blocks = (warps * 32 + threads - 1) / threads;
    Quantize_29437705847334_kernel<<<blocks, threads>>>(x, qbar, qhard, qsoft, onehot, n);
}

// round 4
// speedup vs baseline: 2.0740x; 1.0127x over previous
#include <cuda_runtime.h>
#include <cuda_bf16.h>

// k_i = exp(-c_i^2), c_i = -2 + 0.25*i  (double-evaluated literals)
__constant__ float K_EXP[16] = {
    0.01831563889245985f, 0.04677062238395898f, 0.10539922456186433f, 0.20961138667265397f,
    0.36787944117144233f, 0.56978282473092210f, 0.77880078307140487f, 0.93941306281347579f,
    1.00000000000000000f, 0.93941306281347579f, 0.77880078307140487f, 0.56978282473092210f,
    0.36787944117144233f, 0.20961138667265397f, 0.10539922456186433f, 0.04677062238395898f
};

// exp(-d) rounds to 1.0f for d <= ~2^-25: tied softmax weights -> argmax picks lower index.
#define TIE_EPS 2.9802322387695312e-8f   // 2^-25

__device__ __forceinline__ void quantize_one(float xv, float& qh, float& qs, int& idx)
{
    // --- hard assignment, replicating reference fp32 boundary behavior ---
    float t = fmaf(xv, 4.0f, 8.0f);
    int lo = (int)floorf(t);
    lo = max(0, min(lo, 15));
    int hi = min(lo + 1, 15);

    float clo = fmaf((float)lo, 0.25f, -2.0f);
    float chi = fmaf((float)hi, 0.25f, -2.0f);
    float dlo = __fsub_rn(xv, clo);
    float dhi = __fsub_rn(xv, chi);
    float plo  = __fmul_rn(dlo, dlo);    // same ops/rounding as reference phi
    float phi_ = __fmul_rn(dhi, dhi);

    // hi wins only if its exp weight is strictly greater after fp32 exp rounding
    idx = (__fsub_rn(plo, phi_) > TIE_EPS) ? hi : lo;
    qh = fmaf((float)idx, 0.25f, -2.0f);

    // --- soft assignment: w_i ∝ exp(0.5*x)^i * exp(-c_i^2) ---
    // pairwise powers shorten the dependency chain vs 15 sequential multiplies
    float r  = __expf(0.5f * xv);
    float r2 = r * r;
    float r4 = r2 * r2;
    float r8 = r4 * r4;
    float pw[16];
    pw[0] = 1.0f; pw[1] = r;       pw[2] = r2;      pw[3] = r2 * r;
    pw[4] = r4;   pw[5] = r4 * r;  pw[6] = r4 * r2; pw[7] = r4 * (r2 * r);
#pragma unroll
    for (int i = 8; i < 16; ++i) pw[i] = pw[i - 8] * r8;

    float num = 0.0f, den = 0.0f;
#pragma unroll
    for (int i = 0; i < 16; ++i) {
        float u = K_EXP[i] * pw[i];
        den += u;
        float ci = fmaf((float)i, 0.25f, -2.0f);   // compile-time constant after unroll
        num = fmaf(ci, u, num);
    }
    qs = __fdividef(num, den);
}

// Each warp handles 128 contiguous elements (4 per lane via float4).
// one_hot (128 rows x 64B = 8KB contiguous) is written with fully coalesced
// STG.128; all output stores use evict-first (streaming) hints since the data
// is write-once and would otherwise thrash L2.
__global__ void Quantize_29437705847334_kernel(
    const float* __restrict__ x,
    float* __restrict__ qbar,
    float* __restrict__ qhard,
    float* __restrict__ qsoft,
    float* __restrict__ onehot,
    int n)
{
    int lane = threadIdx.x & 31;
    int warp_id = (blockIdx.x * blockDim.x + threadIdx.x) >> 5;
    size_t base = (size_t)warp_id * 128;          // warp's first element
    if (base >= (size_t)n) return;

    if (base + 128 <= (size_t)n) {
        size_t e4 = base + (size_t)lane * 4;
        float4 xv = __ldcs(reinterpret_cast<const float4*>(x + e4));

        float qh0, qh1, qh2, qh3, qs0, qs1, qs2, qs3;
        int i0, i1, i2, i3;
        quantize_one(xv.x, qh0, qs0, i0);
        quantize_one(xv.y, qh1, qs1, i1);
        quantize_one(xv.z, qh2, qs2, i2);
        quantize_one(xv.w, qh3, qs3, i3);

        float4 qh = make_float4(qh0, qh1, qh2, qh3);
        float4 qs = make_float4(qs0, qs1, qs2, qs3);
        __stcs(reinterpret_cast<float4*>(qbar  + e4), qh);
        __stcs(reinterpret_cast<float4*>(qhard + e4), qh);
        __stcs(reinterpret_cast<float4*>(qsoft + e4), qs);

        unsigned pack = (unsigned)i0 | ((unsigned)i1 << 4) |
                        ((unsigned)i2 << 8) | ((unsigned)i3 << 12);

        float4* oh = reinterpret_cast<float4*>(onehot + base * 16);
#pragma unroll
        for (int j = 0; j < 16; ++j) {
            int g   = j * 32 + lane;          // float4 slot within warp's 8KB run
            int e   = g >> 2;                 // element 0..127 within warp
            int q4  = (g & 3) << 2;           // first center of this quad
            unsigned pk = __shfl_sync(0xffffffffu, pack, e >> 2);
            int idx_e = (int)((pk >> ((e & 3) * 4)) & 15u);
            float4 v;
            v.x = (idx_e == q4 + 0) ? 1.0f : 0.0f;
            v.y = (idx_e == q4 + 1) ? 1.0f : 0.0f;
            v.z = (idx_e == q4 + 2) ? 1.0f : 0.0f;
            v.w = (idx_e == q4 + 3) ? 1.0f : 0.0f;
            __stcs(oh + g, v);
        }
    } else {
        // scalar tail (n not a multiple of 128)
        for (size_t e = base + lane; e < (size_t)n; e += 32) {
            float qh, qs; int idx;
            quantize_one(x[e], qh, qs, idx);
            qbar[e]  = qh;
            qhard[e] = qh;
            qsoft[e] = qs;
            float* oh = onehot + e * 16;
#pragma unroll
            for (int i = 0; i < 16; ++i) oh[i] = (i == idx) ? 1.0f : 0.0f;
        }
    }
}

extern "C" void kernel_launch(void* const* d_in, const int* in_sizes, int n_in,
                              void* d_out, int out_size)
{
    const float* x = (const float*)d_in[0];
    int n = in_sizes[0];                 // 4,194,304 elements

    float* out    = (float*)d_out;
    float* qbar   = out;
    float* qhard  = out + (size_t)n;
    float* qsoft  = out + (size_t)2 * n;
    float* onehot = out + (size_t)3 * n;

    int warps = (n + 127) / 128;
    int threads = 256;                   // 8 warps/block
    int blocks = (warps * 32 + threads - 1) / threads;
    Quantize_29437705847334_kernel<<<blocks, threads>>>(x, qbar, qhard, qsoft, onehot, n);
}